// round 16
// baseline (speedup 1.0000x reference)
#include <cuda_runtime.h>

#define NPTS   2048
#define MPTS   64
#define KNB    32
#define NFRM   64      // B*T = 4*16
#define TT     16
#define COUTC  1024
#define RAD2   0.49f
#define XYZ_OUT_ELEMS (NFRM * MPTS * 3)   // 12288

// ---------------- scratch (static device globals; no allocation) ----------------
__device__ float4 g_anchors[NFRM * MPTS];                 // anchor coords per frame
__device__ float  g_disp[(size_t)NFRM * 3 * 96 * MPTS];   // [f][coord][tap*32+k][m]

// ============================================================================
// Kernel 1: furthest point sampling. One block per frame (64 blocks, 256 thr).
// Matches jax scan: idx[0]=0; each step min-updates d2 vs last point, argmax
// (first occurrence on ties). Arithmetic in rn ops, XLA order ((dx2+dy2)+dz2).
// ============================================================================
__global__ __launch_bounds__(256) void fps_kernel(const float* __restrict__ xyzs,
                                                  float* __restrict__ out)
{
    __shared__ float sx[NPTS], sy[NPTS], sz[NPTS];
    __shared__ float rv[8];
    __shared__ int   ri[8];
    __shared__ int   sLast;

    const int f   = blockIdx.x;
    const int tid = threadIdx.x;
    const int lane = tid & 31, wid = tid >> 5;
    const float* src = xyzs + (size_t)f * NPTS * 3;

    for (int i = tid; i < NPTS; i += 256) {
        sx[i] = src[3 * i + 0];
        sy[i] = src[3 * i + 1];
        sz[i] = src[3 * i + 2];
    }
    __syncthreads();

    // this thread's 8 points in registers
    float px[8], py[8], pz[8], d2[8];
#pragma unroll
    for (int j = 0; j < 8; j++) {
        int p = tid + 256 * j;
        px[j] = sx[p]; py[j] = sy[p]; pz[j] = sz[p];
        d2[j] = 1e10f;
    }

    int last = 0;
    for (int m = 0; m < MPTS; m++) {
        float lx = sx[last], ly = sy[last], lz = sz[last];
        if (tid == 0) {
            out[(size_t)f * MPTS * 3 + m * 3 + 0] = lx;
            out[(size_t)f * MPTS * 3 + m * 3 + 1] = ly;
            out[(size_t)f * MPTS * 3 + m * 3 + 2] = lz;
            g_anchors[f * MPTS + m] = make_float4(lx, ly, lz, 0.f);
        }

        float bv = -1.0f;
        int   bi = 0x7fffffff;
#pragma unroll
        for (int j = 0; j < 8; j++) {
            float dx = __fsub_rn(px[j], lx);
            float dy = __fsub_rn(py[j], ly);
            float dz = __fsub_rn(pz[j], lz);
            float d  = __fadd_rn(__fadd_rn(__fmul_rn(dx, dx), __fmul_rn(dy, dy)),
                                 __fmul_rn(dz, dz));
            d = fminf(d2[j], d);
            d2[j] = d;
            int p = tid + 256 * j;
            if (d > bv || (d == bv && p < bi)) { bv = d; bi = p; }
        }
        // warp argmax with smaller-index tie break
#pragma unroll
        for (int off = 16; off > 0; off >>= 1) {
            float ov = __shfl_down_sync(0xffffffffu, bv, off);
            int   oi = __shfl_down_sync(0xffffffffu, bi, off);
            if (ov > bv || (ov == bv && oi < bi)) { bv = ov; bi = oi; }
        }
        if (lane == 0) { rv[wid] = bv; ri[wid] = bi; }
        __syncthreads();
        if (tid == 0) {
            float v = rv[0]; int b = ri[0];
#pragma unroll
            for (int w = 1; w < 8; w++)
                if (rv[w] > v || (rv[w] == v && ri[w] < b)) { v = rv[w]; b = ri[w]; }
            sLast = b;
        }
        __syncthreads();
        last = sLast;
    }
}

// ============================================================================
// Kernel 2: ball query + displacement gather. Block per (tap, frame): 192 blocks.
// Warp-per-anchor ballot masks over 2048 points, warp prefix-scan extracts the
// first 32 in-radius indices in index order (pointnet2 semantics, pad with
// first valid / 0). Then a transposed coalesced write of displacements into
// g_disp with m minor so kernel 3 reads conflict-free shared memory.
// ============================================================================
__global__ __launch_bounds__(256) void ballquery_kernel(const float* __restrict__ xyzs)
{
    __shared__ float nx[NPTS], ny[NPTS], nz[NPTS];
    __shared__ float ax[MPTS], ay[MPTS], az[MPTS];
    __shared__ unsigned wmask[8][64];
    __shared__ int idxw[8][KNB];
    __shared__ int idxAll[MPTS * KNB];

    const int tap = blockIdx.x;        // 0,1,2  -> dt = tap-1
    const int f   = blockIdx.y;
    const int b   = f >> 4, t = f & 15;
    int ts = t + (tap - 1);
    ts = ts < 0 ? 0 : (ts > TT - 1 ? TT - 1 : ts);
    const float* src = xyzs + (size_t)(b * TT + ts) * NPTS * 3;

    const int tid = threadIdx.x;
    const int lane = tid & 31, w = tid >> 5;

    for (int i = tid; i < NPTS; i += 256) {
        nx[i] = src[3 * i + 0];
        ny[i] = src[3 * i + 1];
        nz[i] = src[3 * i + 2];
    }
    for (int i = tid; i < MPTS; i += 256) {
        float4 a = g_anchors[f * MPTS + i];
        ax[i] = a.x; ay[i] = a.y; az[i] = a.z;
    }
    __syncthreads();

    for (int pass = 0; pass < 8; pass++) {
        const int m = pass * 8 + w;
        const float mx = ax[m], my = ay[m], mz = az[m];

        for (int seg = 0; seg < 64; seg++) {
            int p = seg * 32 + lane;
            float dx = __fsub_rn(nx[p], mx);
            float dy = __fsub_rn(ny[p], my);
            float dz = __fsub_rn(nz[p], mz);
            float d  = __fadd_rn(__fadd_rn(__fmul_rn(dx, dx), __fmul_rn(dy, dy)),
                                 __fmul_rn(dz, dz));
            unsigned msk = __ballot_sync(0xffffffffu, d < RAD2);
            if (lane == 0) wmask[w][seg] = msk;
        }
        __syncwarp();

        unsigned w0 = wmask[w][2 * lane];
        unsigned w1 = wmask[w][2 * lane + 1];
        int c0 = __popc(w0);
        int c  = c0 + __popc(w1);
        int incl = c;
#pragma unroll
        for (int off = 1; off < 32; off <<= 1) {
            int nn = __shfl_up_sync(0xffffffffu, incl, off);
            if (lane >= off) incl += nn;
        }
        const int total = __shfl_sync(0xffffffffu, incl, 31);
        const int excl  = incl - c;

        int off = excl;
        unsigned bits = w0;
        int base = lane * 64;
        while (bits && off < KNB) {
            int bp = __ffs(bits) - 1;
            idxw[w][off++] = base + bp;
            bits &= bits - 1;
        }
        off = excl + c0;
        bits = w1;
        base = lane * 64 + 32;
        while (bits && off < KNB) {
            int bp = __ffs(bits) - 1;
            idxw[w][off++] = base + bp;
            bits &= bits - 1;
        }
        __syncwarp();

        int cnt  = total < KNB ? total : KNB;
        int padi = total > 0 ? idxw[w][0] : 0;
        int v    = (lane < cnt) ? idxw[w][lane] : padi;
        idxAll[m * KNB + lane] = v;
        __syncwarp();
    }
    __syncthreads();

    // transposed write: g_disp[((f*3+coord)*96 + tap*32+k) * 64 + m]
    float* gd = g_disp + (size_t)f * 3 * 96 * MPTS;
    for (int e = tid; e < 3 * KNB * MPTS; e += 256) {
        int m = e & 63;
        int r = e >> 6;          // 0..95: coord*32 + k
        int k = r & 31;
        int coord = r >> 5;
        int idx = idxAll[m * KNB + k];
        float av = (coord == 0) ? ax[m] : (coord == 1) ? ay[m] : az[m];
        float nv = (coord == 0) ? nx[idx] : (coord == 1) ? ny[idx] : nz[idx];
        gd[(coord * 96 + tap * KNB + k) * MPTS + m] = __fsub_rn(nv, av);
    }
}

// ============================================================================
// Kernel 3: 1x1 conv (COUT=1024) + ReLU + max over K + sum over taps.
// Block per (frame, 64-channel chunk, half-of-m): grid (32, 64), 256 threads.
// Thread: ml = tid&31 (one m), 8 channels in registers. Smem disp tile 36KB,
// m minor -> conflict-free broadcast-free LDS. relu+max folds to fmax with
// init 0 since relu outputs are >= 0.
// ============================================================================
__global__ __launch_bounds__(256) void feat_kernel(const float* __restrict__ w_d,
                                                   float* __restrict__ out)
{
    __shared__ float sm[3 * 96 * 32];   // [coord][kk][ml]

    const int bx    = blockIdx.x;       // 0..31
    const int f     = blockIdx.y;
    const int chunk = bx >> 1;          // 0..15 (64 channels each)
    const int h     = bx & 1;           // which half of m
    const int tid   = threadIdx.x;

    // stage disp tile: rows of 32 consecutive floats (128B), float4 loads
    const float* gsrc = g_disp + (size_t)f * 3 * 96 * MPTS + h * 32;
    const float4* g4 = reinterpret_cast<const float4*>(gsrc);
    float4* s4 = reinterpret_cast<float4*>(sm);
    for (int i = tid; i < 3 * 96 * 8; i += 256) {   // 2304 float4
        int r = i >> 3, cc = i & 7;
        s4[i] = g4[r * 16 + cc];
    }
    __syncthreads();

    const int ml = tid & 31;
    const int cg = tid >> 5;                 // 0..7
    const int cbase = chunk * 64 + cg * 8;

    float4 w[8];
#pragma unroll
    for (int i = 0; i < 8; i++)
        w[i] = reinterpret_cast<const float4*>(w_d)[cbase + i];

    float feat[8];
#pragma unroll
    for (int i = 0; i < 8; i++) feat[i] = 0.f;

#pragma unroll
    for (int tap = 0; tap < 3; tap++) {
        const float dtv = (float)(tap - 1);
        float bias[8], mx[8];
#pragma unroll
        for (int i = 0; i < 8; i++) { bias[i] = w[i].w * dtv; mx[i] = 0.f; }

#pragma unroll 4
        for (int k = 0; k < KNB; k++) {
            int o = (tap * 32 + k) * 32 + ml;
            float dx = sm[o];
            float dy = sm[3072 + o];
            float dz = sm[6144 + o];
#pragma unroll
            for (int i = 0; i < 8; i++) {
                float v = fmaf(w[i].x, dx, fmaf(w[i].y, dy, fmaf(w[i].z, dz, bias[i])));
                mx[i] = fmaxf(mx[i], v);
            }
        }
#pragma unroll
        for (int i = 0; i < 8; i++) feat[i] += mx[i];
    }

    // out features: [f][c][m], base offset after new_xyzs
    float* ob = out + XYZ_OUT_ELEMS + (size_t)f * COUTC * MPTS + h * 32 + ml;
#pragma unroll
    for (int i = 0; i < 8; i++)
        ob[(size_t)(cbase + i) * MPTS] = feat[i];
}

// ============================================================================
extern "C" void kernel_launch(void* const* d_in, const int* in_sizes, int n_in,
                              void* d_out, int out_size)
{
    const float* xyzs = (const float*)d_in[0];   // [4,16,2048,3]
    const float* w_d  = (const float*)d_in[1];   // [1024,4]
    float* out = (float*)d_out;

    fps_kernel<<<NFRM, 256>>>(xyzs, out);
    ballquery_kernel<<<dim3(3, NFRM), 256>>>(xyzs);
    feat_kernel<<<dim3(32, NFRM), 256>>>(w_d, out);
}

// round 17
// speedup vs baseline: 1.3521x; 1.3521x over previous
#include <cuda_runtime.h>

#define NPTS   2048
#define MPTS   64
#define KNB    32
#define NFRM   64      // B*T = 4*16
#define TT     16
#define COUTC  1024
#define RAD2   0.49f
#define XYZ_OUT_ELEMS (NFRM * MPTS * 3)   // 12288

// ---------------- scratch (static device globals; no allocation) ----------------
__device__ float4 g_anchors[NFRM * MPTS];                 // anchor coords per frame
__device__ float  g_disp[(size_t)NFRM * 3 * 96 * MPTS];   // [f][coord][tap*32+k][m]

// ============================================================================
// Kernel 1: furthest point sampling. One block per frame (64 blocks, 256 thr).
// Matches jax scan: idx[0]=0; each step min-updates d2 vs last point, argmax
// (first occurrence on ties). Arithmetic in rn ops, XLA order ((dx2+dy2)+dz2).
// ============================================================================
__global__ __launch_bounds__(256) void fps_kernel(const float* __restrict__ xyzs,
                                                  float* __restrict__ out)
{
    __shared__ float sx[NPTS], sy[NPTS], sz[NPTS];
    __shared__ float rv[8];
    __shared__ int   ri[8];
    __shared__ int   sLast;

    const int f   = blockIdx.x;
    const int tid = threadIdx.x;
    const int lane = tid & 31, wid = tid >> 5;
    const float* src = xyzs + (size_t)f * NPTS * 3;

    for (int i = tid; i < NPTS; i += 256) {
        sx[i] = src[3 * i + 0];
        sy[i] = src[3 * i + 1];
        sz[i] = src[3 * i + 2];
    }
    __syncthreads();

    // this thread's 8 points in registers
    float px[8], py[8], pz[8], d2[8];
#pragma unroll
    for (int j = 0; j < 8; j++) {
        int p = tid + 256 * j;
        px[j] = sx[p]; py[j] = sy[p]; pz[j] = sz[p];
        d2[j] = 1e10f;
    }

    int last = 0;
    for (int m = 0; m < MPTS; m++) {
        float lx = sx[last], ly = sy[last], lz = sz[last];
        if (tid == 0) {
            out[(size_t)f * MPTS * 3 + m * 3 + 0] = lx;
            out[(size_t)f * MPTS * 3 + m * 3 + 1] = ly;
            out[(size_t)f * MPTS * 3 + m * 3 + 2] = lz;
            g_anchors[f * MPTS + m] = make_float4(lx, ly, lz, 0.f);
        }

        float bv = -1.0f;
        int   bi = 0x7fffffff;
#pragma unroll
        for (int j = 0; j < 8; j++) {
            float dx = __fsub_rn(px[j], lx);
            float dy = __fsub_rn(py[j], ly);
            float dz = __fsub_rn(pz[j], lz);
            float d  = __fadd_rn(__fadd_rn(__fmul_rn(dx, dx), __fmul_rn(dy, dy)),
                                 __fmul_rn(dz, dz));
            d = fminf(d2[j], d);
            d2[j] = d;
            int p = tid + 256 * j;
            if (d > bv || (d == bv && p < bi)) { bv = d; bi = p; }
        }
        // warp argmax with smaller-index tie break
#pragma unroll
        for (int off = 16; off > 0; off >>= 1) {
            float ov = __shfl_down_sync(0xffffffffu, bv, off);
            int   oi = __shfl_down_sync(0xffffffffu, bi, off);
            if (ov > bv || (ov == bv && oi < bi)) { bv = ov; bi = oi; }
        }
        if (lane == 0) { rv[wid] = bv; ri[wid] = bi; }
        __syncthreads();
        if (tid == 0) {
            float v = rv[0]; int b = ri[0];
#pragma unroll
            for (int w = 1; w < 8; w++)
                if (rv[w] > v || (rv[w] == v && ri[w] < b)) { v = rv[w]; b = ri[w]; }
            sLast = b;
        }
        __syncthreads();
        last = sLast;
    }
}

// ============================================================================
// Kernel 2: ball query + displacement gather. Block per (tap, frame): 192 blocks.
// Warp-per-anchor ballot masks over 2048 points, warp prefix-scan extracts the
// first 32 in-radius indices in index order (pointnet2 semantics, pad with
// first valid / 0). Then a transposed coalesced write of displacements into
// g_disp with m minor so kernel 3 reads conflict-free shared memory.
// ============================================================================
__global__ __launch_bounds__(256) void ballquery_kernel(const float* __restrict__ xyzs)
{
    __shared__ float nx[NPTS], ny[NPTS], nz[NPTS];
    __shared__ float ax[MPTS], ay[MPTS], az[MPTS];
    __shared__ unsigned wmask[8][64];
    __shared__ int idxw[8][KNB];
    __shared__ int idxAll[MPTS * KNB];

    const int tap = blockIdx.x;        // 0,1,2  -> dt = tap-1
    const int f   = blockIdx.y;
    const int b   = f >> 4, t = f & 15;
    int ts = t + (tap - 1);
    ts = ts < 0 ? 0 : (ts > TT - 1 ? TT - 1 : ts);
    const float* src = xyzs + (size_t)(b * TT + ts) * NPTS * 3;

    const int tid = threadIdx.x;
    const int lane = tid & 31, w = tid >> 5;

    for (int i = tid; i < NPTS; i += 256) {
        nx[i] = src[3 * i + 0];
        ny[i] = src[3 * i + 1];
        nz[i] = src[3 * i + 2];
    }
    for (int i = tid; i < MPTS; i += 256) {
        float4 a = g_anchors[f * MPTS + i];
        ax[i] = a.x; ay[i] = a.y; az[i] = a.z;
    }
    __syncthreads();

    for (int pass = 0; pass < 8; pass++) {
        const int m = pass * 8 + w;
        const float mx = ax[m], my = ay[m], mz = az[m];

        for (int seg = 0; seg < 64; seg++) {
            int p = seg * 32 + lane;
            float dx = __fsub_rn(nx[p], mx);
            float dy = __fsub_rn(ny[p], my);
            float dz = __fsub_rn(nz[p], mz);
            float d  = __fadd_rn(__fadd_rn(__fmul_rn(dx, dx), __fmul_rn(dy, dy)),
                                 __fmul_rn(dz, dz));
            unsigned msk = __ballot_sync(0xffffffffu, d < RAD2);
            if (lane == 0) wmask[w][seg] = msk;
        }
        __syncwarp();

        unsigned w0 = wmask[w][2 * lane];
        unsigned w1 = wmask[w][2 * lane + 1];
        int c0 = __popc(w0);
        int c  = c0 + __popc(w1);
        int incl = c;
#pragma unroll
        for (int off = 1; off < 32; off <<= 1) {
            int nn = __shfl_up_sync(0xffffffffu, incl, off);
            if (lane >= off) incl += nn;
        }
        const int total = __shfl_sync(0xffffffffu, incl, 31);
        const int excl  = incl - c;

        int off = excl;
        unsigned bits = w0;
        int base = lane * 64;
        while (bits && off < KNB) {
            int bp = __ffs(bits) - 1;
            idxw[w][off++] = base + bp;
            bits &= bits - 1;
        }
        off = excl + c0;
        bits = w1;
        base = lane * 64 + 32;
        while (bits && off < KNB) {
            int bp = __ffs(bits) - 1;
            idxw[w][off++] = base + bp;
            bits &= bits - 1;
        }
        __syncwarp();

        int cnt  = total < KNB ? total : KNB;
        int padi = total > 0 ? idxw[w][0] : 0;
        int v    = (lane < cnt) ? idxw[w][lane] : padi;
        idxAll[m * KNB + lane] = v;
        __syncwarp();
    }
    __syncthreads();

    // transposed write: g_disp[((f*3+coord)*96 + tap*32+k) * 64 + m]
    float* gd = g_disp + (size_t)f * 3 * 96 * MPTS;
    for (int e = tid; e < 3 * KNB * MPTS; e += 256) {
        int m = e & 63;
        int r = e >> 6;          // 0..95: coord*32 + k
        int k = r & 31;
        int coord = r >> 5;
        int idx = idxAll[m * KNB + k];
        float av = (coord == 0) ? ax[m] : (coord == 1) ? ay[m] : az[m];
        float nv = (coord == 0) ? nx[idx] : (coord == 1) ? ny[idx] : nz[idx];
        gd[(coord * 96 + tap * KNB + k) * MPTS + m] = __fsub_rn(nv, av);
    }
}

// ============================================================================
// Kernel 3: 1x1 conv (COUT=1024) + ReLU + max over K + sum over taps.
// Block per (frame, 64-channel chunk, half-of-m): grid (32, 64), 256 threads.
// Thread: ml = tid&31 (one m), 8 channels in registers. Smem disp tile 36KB,
// m minor -> conflict-free broadcast-free LDS. relu+max folds to fmax with
// init 0 since relu outputs are >= 0.
// ============================================================================
__global__ __launch_bounds__(256) void feat_kernel(const float* __restrict__ w_d,
                                                   float* __restrict__ out)
{
    __shared__ float sm[3 * 96 * 32];   // [coord][kk][ml]

    const int bx    = blockIdx.x;       // 0..31
    const int f     = blockIdx.y;
    const int chunk = bx >> 1;          // 0..15 (64 channels each)
    const int h     = bx & 1;           // which half of m
    const int tid   = threadIdx.x;

    // stage disp tile: rows of 32 consecutive floats (128B), float4 loads
    const float* gsrc = g_disp + (size_t)f * 3 * 96 * MPTS + h * 32;
    const float4* g4 = reinterpret_cast<const float4*>(gsrc);
    float4* s4 = reinterpret_cast<float4*>(sm);
    for (int i = tid; i < 3 * 96 * 8; i += 256) {   // 2304 float4
        int r = i >> 3, cc = i & 7;
        s4[i] = g4[r * 16 + cc];
    }
    __syncthreads();

    const int ml = tid & 31;
    const int cg = tid >> 5;                 // 0..7
    const int cbase = chunk * 64 + cg * 8;

    float4 w[8];
#pragma unroll
    for (int i = 0; i < 8; i++)
        w[i] = reinterpret_cast<const float4*>(w_d)[cbase + i];

    float feat[8];
#pragma unroll
    for (int i = 0; i < 8; i++) feat[i] = 0.f;

#pragma unroll
    for (int tap = 0; tap < 3; tap++) {
        const float dtv = (float)(tap - 1);
        float bias[8], mx[8];
#pragma unroll
        for (int i = 0; i < 8; i++) { bias[i] = w[i].w * dtv; mx[i] = 0.f; }

#pragma unroll 4
        for (int k = 0; k < KNB; k++) {
            int o = (tap * 32 + k) * 32 + ml;
            float dx = sm[o];
            float dy = sm[3072 + o];
            float dz = sm[6144 + o];
#pragma unroll
            for (int i = 0; i < 8; i++) {
                float v = fmaf(w[i].x, dx, fmaf(w[i].y, dy, fmaf(w[i].z, dz, bias[i])));
                mx[i] = fmaxf(mx[i], v);
            }
        }
#pragma unroll
        for (int i = 0; i < 8; i++) feat[i] += mx[i];
    }

    // out features: [f][c][m], base offset after new_xyzs
    float* ob = out + XYZ_OUT_ELEMS + (size_t)f * COUTC * MPTS + h * 32 + ml;
#pragma unroll
    for (int i = 0; i < 8; i++)
        ob[(size_t)(cbase + i) * MPTS] = feat[i];
}

// ============================================================================
extern "C" void kernel_launch(void* const* d_in, const int* in_sizes, int n_in,
                              void* d_out, int out_size)
{
    const float* xyzs = (const float*)d_in[0];   // [4,16,2048,3]
    const float* w_d  = (const float*)d_in[1];   // [1024,4]
    float* out = (float*)d_out;

    fps_kernel<<<NFRM, 256>>>(xyzs, out);
    ballquery_kernel<<<dim3(3, NFRM), 256>>>(xyzs);
    feat_kernel<<<dim3(32, NFRM), 256>>>(w_d, out);
}